// round 8
// baseline (speedup 1.0000x reference)
#include <cuda_runtime.h>
#include <cstdint>
#include <cstddef>

#define BATCH 4096
#define T_SEQ 512
#define SDIM  16
#define ODIM  8
#define IDIM  4
#define RS    8
#define CH    64
#define LCH   8
#define NB    2
#define TPB   128
#define NTYPE 2
#define NBX   (BATCH/(TPB*NB))   // 16 batch stripes

typedef unsigned long long ull;

__device__ float g_M [RS*256];
__device__ float g_Kg[RS*128];
__device__ float g_Ng[RS*64];
__device__ float g_Phi[NTYPE*256];
__device__ float g_W  [NTYPE*16*96];            // [type][s][j*12 + q] (q: 0..7 z, 8..11 u)
__device__ float g_xe [(size_t)CH*SDIM*BATCH];  // chunk-end states [c][s][b]
__device__ int   g_flag[CH*NBX];
__device__ int   g_ticket;

// ---------- f32x2 helpers ----------
__device__ __forceinline__ ull fpair(float a, float b){
  ull r; asm("mov.b64 %0, {%1,%2};" : "=l"(r) : "f"(a), "f"(b)); return r;
}
__device__ __forceinline__ ull fdup(float a){ return fpair(a,a); }
__device__ __forceinline__ void unpack2(ull p, float& a, float& b){
  asm("mov.b64 {%0,%1}, %2;" : "=f"(a), "=f"(b) : "l"(p));
}
__device__ __forceinline__ void ffma2(ull& d, ull a, ull b){
  asm("fma.rn.f32x2 %0, %1, %2, %0;" : "+l"(d) : "l"(a), "l"(b));
}

// ---------- fully unrolled 4x4 inverse ----------
__device__ __forceinline__ void inv4x4(const float* m, int ld, float* inv){
  float a00=m[0],      a01=m[1],      a02=m[2],      a03=m[3];
  float a10=m[ld],     a11=m[ld+1],   a12=m[ld+2],   a13=m[ld+3];
  float a20=m[2*ld],   a21=m[2*ld+1], a22=m[2*ld+2], a23=m[2*ld+3];
  float a30=m[3*ld],   a31=m[3*ld+1], a32=m[3*ld+2], a33=m[3*ld+3];
  float s0=a00*a11-a01*a10, s1=a00*a12-a02*a10, s2=a00*a13-a03*a10;
  float s3=a01*a12-a02*a11, s4=a01*a13-a03*a11, s5=a02*a13-a03*a12;
  float c5=a22*a33-a23*a32, c4=a21*a33-a23*a31, c3=a21*a32-a22*a31;
  float c2=a20*a33-a23*a30, c1=a20*a32-a22*a30, c0=a20*a31-a21*a30;
  float det=s0*c5-s1*c4+s2*c3+s3*c2-s4*c1+s5*c0;
  float id=1.f/det;
  inv[0] =( a11*c5-a12*c4+a13*c3)*id;
  inv[1] =(-a01*c5+a02*c4-a03*c3)*id;
  inv[2] =( a31*s5-a32*s4+a33*s3)*id;
  inv[3] =(-a21*s5+a22*s4-a23*s3)*id;
  inv[4] =(-a10*c5+a12*c2-a13*c1)*id;
  inv[5] =( a00*c5-a02*c2+a03*c1)*id;
  inv[6] =(-a30*s5+a32*s2-a33*s1)*id;
  inv[7] =( a20*s5-a22*s2+a23*s1)*id;
  inv[8] =( a10*c4-a11*c2+a13*c0)*id;
  inv[9] =(-a00*c4+a01*c2-a03*c0)*id;
  inv[10]=( a30*s4-a31*s2+a33*s0)*id;
  inv[11]=(-a20*s4+a21*s2-a23*s0)*id;
  inv[12]=(-a10*c3+a11*c1-a12*c0)*id;
  inv[13]=( a00*c3-a01*c1+a02*c0)*id;
  inv[14]=(-a30*s3+a31*s1-a32*s0)*id;
  inv[15]=( a20*s3-a21*s1+a22*s0)*id;
}

// K1: Riccati + W/Phi composition + flag/ticket reset. 1 block, 256 threads.
__global__ void riccati_kernel(const float* __restrict__ A_, const float* __restrict__ B_,
                               const float* __restrict__ C_, const float* __restrict__ Q_,
                               const float* __restrict__ R_)
{
  __shared__ float sA[256], sQ[256], sC[128], sB[64], sR[64], sCA[128], sCB[32];
  __shared__ float P[256], Tm[256], Pp[256], CP[128], S8[64], Sinv[64], KK[128];
  __shared__ float BufA[256], BufB[256];
  const int t = threadIdx.x;
  const int s = t>>4, j = t&15;

  for (int e=t; e<CH*NBX; e+=256) g_flag[e]=0;     // reset chain state
  if (t==0) g_ticket=0;

  sA[t]=A_[t]; sQ[t]=Q_[t];
  P[t] = (s==j)?1.f:0.f;
  if (t<128) sC[t]=C_[t];
  if (t<64){ sB[t]=B_[t]; sR[t]=R_[t]; }
  __syncthreads();
  if (t<128){ int o=t>>4, jj=t&15; float a=0.f;
    #pragma unroll
    for(int m=0;m<16;m++) a+=sC[o*16+m]*sA[m*16+jj];
    sCA[t]=a; }
  if (t<32){ int o=t>>2, ii=t&3; float a=0.f;
    #pragma unroll
    for(int m=0;m<16;m++) a+=sC[o*16+m]*sB[m*4+ii];
    sCB[t]=a; }
  __syncthreads();

  for (int k=0;k<RS;k++){
    { float a=0.f;                                    // Tm = A @ P
      #pragma unroll
      for(int m=0;m<16;m++) a+=sA[s*16+m]*P[m*16+j];
      Tm[t]=a; }
    __syncthreads();
    { float a=sQ[t];                                  // Pp = Tm A^T + Q
      #pragma unroll
      for(int m=0;m<16;m++) a+=Tm[s*16+m]*sA[j*16+m];
      Pp[t]=a; }
    __syncthreads();
    if (t<128){ int o=t>>4, jj=t&15; float a=0.f;     // CP = C @ Pp
      #pragma unroll
      for(int m=0;m<16;m++) a+=sC[o*16+m]*Pp[m*16+jj];
      CP[t]=a; }
    __syncthreads();
    if (t<64){ int o=t>>3, p=t&7; float a=sR[t];      // S = CP C^T + R
      #pragma unroll
      for(int m=0;m<16;m++) a+=CP[o*16+m]*sC[p*16+m];
      S8[t]=a; }
    __syncthreads();
    if (t==0){                                        // 8x8 SPD inverse via Schur
      float Ai[16]; inv4x4(&S8[0], 8, Ai);
      float W[16];
      #pragma unroll
      for(int i4=0;i4<4;i4++)
        #pragma unroll
        for(int j4=0;j4<4;j4++){ float a=0.f;
          #pragma unroll
          for(int m=0;m<4;m++) a+=S8[(4+i4)*8+m]*Ai[m*4+j4];
          W[i4*4+j4]=a; }
      float Sc[16];
      #pragma unroll
      for(int i4=0;i4<4;i4++)
        #pragma unroll
        for(int j4=0;j4<4;j4++){ float a=S8[(4+i4)*8+4+j4];
          #pragma unroll
          for(int m=0;m<4;m++) a-=W[i4*4+m]*S8[m*8+4+j4];
          Sc[i4*4+j4]=a; }
      float Sci[16]; inv4x4(Sc, 4, Sci);
      float X21[16];
      #pragma unroll
      for(int i4=0;i4<4;i4++)
        #pragma unroll
        for(int j4=0;j4<4;j4++){ float a=0.f;
          #pragma unroll
          for(int m=0;m<4;m++) a+=Sci[i4*4+m]*W[m*4+j4];
          X21[i4*4+j4]=-a; }
      float X11[16];
      #pragma unroll
      for(int i4=0;i4<4;i4++)
        #pragma unroll
        for(int j4=0;j4<4;j4++){ float a=Ai[i4*4+j4];
          #pragma unroll
          for(int m=0;m<4;m++) a-=W[m*4+i4]*X21[m*4+j4];
          X11[i4*4+j4]=a; }
      #pragma unroll
      for(int o=0;o<8;o++)
        #pragma unroll
        for(int p=0;p<8;p++){
          float v;
          if (o<4 && p<4) v=X11[o*4+p];
          else if (o<4)   v=X21[(p-4)*4+o];
          else if (p<4)   v=X21[(o-4)*4+p];
          else            v=Sci[(o-4)*4+(p-4)];
          Sinv[o*8+p]=v; }
    }
    __syncthreads();
    if (t<128){ int ss=t>>3, o=t&7; float a=0.f;      // K = CP^T Sinv
      #pragma unroll
      for(int p=0;p<8;p++) a+=CP[p*16+ss]*Sinv[p*8+o];
      KK[t]=a; }
    __syncthreads();
    { float a=Pp[t], mg=sA[t];                        // P_post, M_k
      #pragma unroll
      for(int o=0;o<8;o++){ float kv=KK[s*8+o]; a-=kv*CP[o*16+j]; mg-=kv*sCA[o*16+j]; }
      P[t]=a;
      g_M[k*256+t]=mg; }
    if (t<128) g_Kg[k*128+t]=KK[t];
    if (t<64){ int ss=t>>2, ii=t&3; float a=sB[t];    // N_k
      #pragma unroll
      for(int o=0;o<8;o++) a-=KK[ss*8+o]*sCB[o*4+ii];
      g_Ng[k*64+t]=a; }
    __syncthreads();
  }

  // Per chunk type tt: suffix products; Wz_j=S_j K_j, Wu_j=S_j N_j; Phi = full product
  for (int tt=0; tt<NTYPE; tt++){
    float* Sb = BufA; float* Sn = BufB;
    Sb[t] = (s==j)?1.f:0.f;
    __syncthreads();
    for (int jj=LCH-1; jj>=0; jj--){
      const int k = (tt==0)? jj : (RS-1);
      if (t<128){ int ss=t>>3, o=t&7; float a=0.f;    // Wz
        #pragma unroll
        for(int m=0;m<16;m++) a+=Sb[ss*16+m]*g_Kg[k*128+m*8+o];
        g_W[(tt*16+ss)*96 + jj*12 + o] = a; }
      else { int e=t-128; int ss=e>>2, ii=e&3;        // Wu
        if (e<64){ float a=0.f;
          #pragma unroll
          for(int m=0;m<16;m++) a+=Sb[ss*16+m]*g_Ng[k*64+m*4+ii];
          g_W[(tt*16+ss)*96 + jj*12 + 8 + ii] = a; } }
      { float a=0.f;                                  // S = S @ M_k
        #pragma unroll
        for(int m=0;m<16;m++) a+=Sb[s*16+m]*g_M[k*256+m*16+j];
        Sn[t]=a; }
      __syncthreads();
      float* tmp=Sb; Sb=Sn; Sn=tmp;
    }
    g_Phi[tt*256+t]=Sb[t];
    __syncthreads();
  }
}

// Fused single-pass chained scan: d-phase + chain link + output phase per (chunk, stripe).
__global__ void __launch_bounds__(TPB) scan_kernel(const float* __restrict__ obs,
                                                   const float* __restrict__ u,
                                                   const float* __restrict__ x0,
                                                   float* __restrict__ out)
{
  __shared__ ull sW[16*96];     // 12KB
  __shared__ ull sM[LCH*256];   // 16KB
  __shared__ ull sK[LCH*128];   // 8KB
  __shared__ ull sN[LCH*64];    // 4KB
  __shared__ ull sPhi[256];     // 2KB
  __shared__ int sTicket;
  const int tid = threadIdx.x;
  if (tid==0) sTicket = atomicAdd(&g_ticket, 1);
  __syncthreads();
  const int ticket = sTicket;
  const int c  = ticket >> 4;      // chunk-major: all stripe-chains advance in parallel
  const int bx = ticket & (NBX-1);
  const bool trans = (c==0);
  const int type = trans?0:1;

  for (int idx=tid; idx<16*96; idx+=TPB) sW[idx]=fdup(g_W[type*1536+idx]);
  const int nset = trans?LCH:1;
  for (int idx=tid; idx<nset*256; idx+=TPB){ int i=idx>>8,e=idx&255; int kk=trans?i:(RS-1); sM[idx]=fdup(g_M[kk*256+e]); }
  for (int idx=tid; idx<nset*128; idx+=TPB){ int i=idx>>7,e=idx&127; int kk=trans?i:(RS-1); sK[idx]=fdup(g_Kg[kk*128+e]); }
  for (int idx=tid; idx<nset*64;  idx+=TPB){ int i=idx>>6,e=idx&63;  int kk=trans?i:(RS-1); sN[idx]=fdup(g_Ng[kk*64+e]); }
  for (int idx=tid; idx<256; idx+=TPB) sPhi[idx]=fdup(g_Phi[type*256+idx]);
  __syncthreads();

  const int b0 = bx*(TPB*NB) + tid*NB;
  const int k0 = c*LCH;
  const float* ob0 = obs + ((size_t)b0*T_SEQ + k0)*ODIM;
  const float* ob1 = ob0 + (size_t)T_SEQ*ODIM;
  const float* uu0 = u   + ((size_t)b0*T_SEQ + k0)*IDIM;
  const float* uu1 = uu0 + (size_t)T_SEQ*IDIM;

  // --- d phase: chunk response from zero state (resp body) ---
  ull dacc[SDIM];
  #pragma unroll
  for (int s=0;s<SDIM;s++) dacc[s]=0ull;
  for (int jj=0;jj<LCH;jj++){
    float4 z0a = *(const float4*)(ob0 + jj*ODIM);
    float4 z0b = *(const float4*)(ob0 + jj*ODIM + 4);
    float4 z1a = *(const float4*)(ob1 + jj*ODIM);
    float4 z1b = *(const float4*)(ob1 + jj*ODIM + 4);
    float4 v0  = *(const float4*)(uu0 + jj*IDIM);
    float4 v1  = *(const float4*)(uu1 + jj*IDIM);
    ull ip[12];
    ip[0]=fpair(z0a.x,z1a.x); ip[1]=fpair(z0a.y,z1a.y);
    ip[2]=fpair(z0a.z,z1a.z); ip[3]=fpair(z0a.w,z1a.w);
    ip[4]=fpair(z0b.x,z1b.x); ip[5]=fpair(z0b.y,z1b.y);
    ip[6]=fpair(z0b.z,z1b.z); ip[7]=fpair(z0b.w,z1b.w);
    ip[8]=fpair(v0.x,v1.x);   ip[9]=fpair(v0.y,v1.y);
    ip[10]=fpair(v0.z,v1.z);  ip[11]=fpair(v0.w,v1.w);
    #pragma unroll
    for (int s=0;s<SDIM;s++){
      const ulonglong2* Wr = (const ulonglong2*)&sW[s*96 + jj*12];
      ull a = dacc[s];
      #pragma unroll
      for (int q=0;q<6;q++){
        ulonglong2 w = Wr[q];
        ffma2(a, w.x, ip[2*q]);
        ffma2(a, w.y, ip[2*q+1]);
      }
      dacc[s]=a;
    }
  }

  // --- chain: wait for predecessor, get x_start ---
  ull xs[SDIM];
  if (c==0){
    #pragma unroll
    for (int s=0;s<SDIM;s++){ float v=x0[s]; xs[s]=fpair(v,v); }
  } else {
    if (tid==0){
      while (atomicAdd(&g_flag[(c-1)*NBX+bx],0)==0) __nanosleep(64);
    }
    __syncthreads();
    #pragma unroll
    for (int s=0;s<SDIM;s++)
      xs[s]=__ldcg((const ull*)&g_xe[((size_t)((c-1)*16+s))*BATCH + b0]);
  }

  // --- x_end = Phi x_start + d; publish ---
  {
    const ulonglong2* P2 = (const ulonglong2*)sPhi;
    #pragma unroll
    for (int s=0;s<SDIM;s++){
      ull a = dacc[s];
      #pragma unroll
      for (int jj=0;jj<8;jj++){
        ulonglong2 mm = P2[s*8+jj];
        ffma2(a, mm.x, xs[2*jj]);
        ffma2(a, mm.y, xs[2*jj+1]);
      }
      *(ull*)&g_xe[((size_t)(c*16+s))*BATCH + b0] = a;
    }
    __threadfence();
    __syncthreads();
    if (tid==0) atomicExch(&g_flag[c*NBX+bx], 1);
  }

  // --- output phase: serial recurrence from x_start (P3 body) ---
  ull xp[SDIM];
  #pragma unroll
  for (int s=0;s<SDIM;s++) xp[s]=xs[s];

  for (int i=0;i<LCH;i++){
    const int mi = trans ? i : 0;
    float4 z0a = *(const float4*)(ob0 + i*ODIM);
    float4 z0b = *(const float4*)(ob0 + i*ODIM + 4);
    float4 z1a = *(const float4*)(ob1 + i*ODIM);
    float4 z1b = *(const float4*)(ob1 + i*ODIM + 4);
    float4 v0  = *(const float4*)(uu0 + i*IDIM);
    float4 v1  = *(const float4*)(uu1 + i*IDIM);
    ull zp[8], up[4];
    zp[0]=fpair(z0a.x,z1a.x); zp[1]=fpair(z0a.y,z1a.y);
    zp[2]=fpair(z0a.z,z1a.z); zp[3]=fpair(z0a.w,z1a.w);
    zp[4]=fpair(z0b.x,z1b.x); zp[5]=fpair(z0b.y,z1b.y);
    zp[6]=fpair(z0b.z,z1b.z); zp[7]=fpair(z0b.w,z1b.w);
    up[0]=fpair(v0.x,v1.x);   up[1]=fpair(v0.y,v1.y);
    up[2]=fpair(v0.z,v1.z);   up[3]=fpair(v0.w,v1.w);

    const ulonglong2* M2 = (const ulonglong2*)&sM[mi*256];
    const ulonglong2* K2 = (const ulonglong2*)&sK[mi*128];
    const ulonglong2* N2 = (const ulonglong2*)&sN[mi*64];
    ull acc[SDIM];
    #pragma unroll
    for (int s=0;s<SDIM;s++){
      ulonglong2 k0p = K2[s*4+0];
      ull a = 0ull;
      ffma2(a, k0p.x, zp[0]); ffma2(a, k0p.y, zp[1]);
      ulonglong2 k1p = K2[s*4+1]; ffma2(a, k1p.x, zp[2]); ffma2(a, k1p.y, zp[3]);
      ulonglong2 k2p = K2[s*4+2]; ffma2(a, k2p.x, zp[4]); ffma2(a, k2p.y, zp[5]);
      ulonglong2 k3p = K2[s*4+3]; ffma2(a, k3p.x, zp[6]); ffma2(a, k3p.y, zp[7]);
      ulonglong2 n0p = N2[s*2+0]; ffma2(a, n0p.x, up[0]); ffma2(a, n0p.y, up[1]);
      ulonglong2 n1p = N2[s*2+1]; ffma2(a, n1p.x, up[2]); ffma2(a, n1p.y, up[3]);
      acc[s]=a;
    }
    #pragma unroll
    for (int s=0;s<SDIM;s++){
      ull a = acc[s];
      #pragma unroll
      for (int jj=0;jj<8;jj++){
        ulonglong2 mm = M2[s*8+jj];
        ffma2(a, mm.x, xp[2*jj]);
        ffma2(a, mm.y, xp[2*jj+1]);
      }
      acc[s]=a;
    }
    #pragma unroll
    for (int s=0;s<SDIM;s++) xp[s]=acc[s];

    {
      float a0[SDIM], a1[SDIM];
      #pragma unroll
      for (int s=0;s<SDIM;s++) unpack2(xp[s], a0[s], a1[s]);
      float4* o0 = (float4*)(out + (((size_t)b0*T_SEQ) + (size_t)(k0+i))*SDIM);
      float4* o1 = (float4*)(out + (((size_t)(b0+1)*T_SEQ) + (size_t)(k0+i))*SDIM);
      o0[0]=make_float4(a0[0],a0[1],a0[2],a0[3]);
      o0[1]=make_float4(a0[4],a0[5],a0[6],a0[7]);
      o0[2]=make_float4(a0[8],a0[9],a0[10],a0[11]);
      o0[3]=make_float4(a0[12],a0[13],a0[14],a0[15]);
      o1[0]=make_float4(a1[0],a1[1],a1[2],a1[3]);
      o1[1]=make_float4(a1[4],a1[5],a1[6],a1[7]);
      o1[2]=make_float4(a1[8],a1[9],a1[10],a1[11]);
      o1[3]=make_float4(a1[12],a1[13],a1[14],a1[15]);
    }
  }
}

extern "C" void kernel_launch(void* const* d_in, const int* in_sizes, int n_in,
                              void* d_out, int out_size)
{
  const float* obs = (const float*)d_in[0];
  const float* u   = (const float*)d_in[1];
  const float* A   = (const float*)d_in[2];
  const float* B   = (const float*)d_in[3];
  const float* C   = (const float*)d_in[4];
  const float* Q   = (const float*)d_in[5];
  const float* R   = (const float*)d_in[6];
  const float* x0  = (const float*)d_in[7];
  float* out = (float*)d_out;

  riccati_kernel<<<1, 256>>>(A, B, C, Q, R);
  scan_kernel<<<CH*NBX, TPB>>>(obs, u, x0, out);
}

// round 9
// speedup vs baseline: 1.1961x; 1.1961x over previous
#include <cuda_runtime.h>
#include <cstdint>
#include <cstddef>

#define BATCH 4096
#define T_SEQ 512
#define SDIM  16
#define ODIM  8
#define IDIM  4
#define RS    8
#define CH    64
#define LCH   8
#define NB    2
#define TPB   128
#define NTYPE 2

typedef unsigned long long ull;

__device__ float g_M [RS*256];
__device__ float g_Kg[RS*128];
__device__ float g_Ng[RS*64];
__device__ float g_Phi[NTYPE*256];
__device__ float g_W  [NTYPE*16*96];            // [type][s][j*12 + q] (q: 0..7 z, 8..11 u)
__device__ float g_d [(size_t)CH*SDIM*BATCH];   // [c][s][b]
__device__ float g_xs[(size_t)CH*SDIM*BATCH];   // [c][s][b]

// ---------- f32x2 helpers ----------
__device__ __forceinline__ ull fpair(float a, float b){
  ull r; asm("mov.b64 %0, {%1,%2};" : "=l"(r) : "f"(a), "f"(b)); return r;
}
__device__ __forceinline__ ull fdup(float a){ return fpair(a,a); }
__device__ __forceinline__ void unpack2(ull p, float& a, float& b){
  asm("mov.b64 {%0,%1}, %2;" : "=f"(a), "=f"(b) : "l"(p));
}
__device__ __forceinline__ void ffma2(ull& d, ull a, ull b){
  asm("fma.rn.f32x2 %0, %1, %2, %0;" : "+l"(d) : "l"(a), "l"(b));
}

// ---------- fully unrolled 4x4 inverse ----------
__device__ __forceinline__ void inv4x4(const float* m, int ld, float* inv){
  float a00=m[0],      a01=m[1],      a02=m[2],      a03=m[3];
  float a10=m[ld],     a11=m[ld+1],   a12=m[ld+2],   a13=m[ld+3];
  float a20=m[2*ld],   a21=m[2*ld+1], a22=m[2*ld+2], a23=m[2*ld+3];
  float a30=m[3*ld],   a31=m[3*ld+1], a32=m[3*ld+2], a33=m[3*ld+3];
  float s0=a00*a11-a01*a10, s1=a00*a12-a02*a10, s2=a00*a13-a03*a10;
  float s3=a01*a12-a02*a11, s4=a01*a13-a03*a11, s5=a02*a13-a03*a12;
  float c5=a22*a33-a23*a32, c4=a21*a33-a23*a31, c3=a21*a32-a22*a31;
  float c2=a20*a33-a23*a30, c1=a20*a32-a22*a30, c0=a20*a31-a21*a30;
  float det=s0*c5-s1*c4+s2*c3+s3*c2-s4*c1+s5*c0;
  float id=1.f/det;
  inv[0] =( a11*c5-a12*c4+a13*c3)*id;
  inv[1] =(-a01*c5+a02*c4-a03*c3)*id;
  inv[2] =( a31*s5-a32*s4+a33*s3)*id;
  inv[3] =(-a21*s5+a22*s4-a23*s3)*id;
  inv[4] =(-a10*c5+a12*c2-a13*c1)*id;
  inv[5] =( a00*c5-a02*c2+a03*c1)*id;
  inv[6] =(-a30*s5+a32*s2-a33*s1)*id;
  inv[7] =( a20*s5-a22*s2+a23*s1)*id;
  inv[8] =( a10*c4-a11*c2+a13*c0)*id;
  inv[9] =(-a00*c4+a01*c2-a03*c0)*id;
  inv[10]=( a30*s4-a31*s2+a33*s0)*id;
  inv[11]=(-a20*s4+a21*s2-a23*s0)*id;
  inv[12]=(-a10*c3+a11*c1-a12*c0)*id;
  inv[13]=( a00*c3-a01*c1+a02*c0)*id;
  inv[14]=(-a30*s3+a31*s1-a32*s0)*id;
  inv[15]=( a20*s3-a21*s1+a22*s0)*id;
}

// K1: Riccati (8 exact steps) + W/Phi composition (2 chunk types). 1 block, 256 threads.
__global__ void riccati_kernel(const float* __restrict__ A_, const float* __restrict__ B_,
                               const float* __restrict__ C_, const float* __restrict__ Q_,
                               const float* __restrict__ R_)
{
  __shared__ float sA[256], sQ[256], sC[128], sB[64], sR[64], sCA[128], sCB[32];
  __shared__ float P[256], Tm[256], Pp[256], CP[128], S8[64], Sinv[64], KK[128];
  __shared__ float BufA[256], BufB[256];
  const int t = threadIdx.x;
  const int s = t>>4, j = t&15;

  sA[t]=A_[t]; sQ[t]=Q_[t];
  P[t] = (s==j)?1.f:0.f;
  if (t<128) sC[t]=C_[t];
  if (t<64){ sB[t]=B_[t]; sR[t]=R_[t]; }
  __syncthreads();
  if (t<128){ int o=t>>4, jj=t&15; float a=0.f;
    #pragma unroll
    for(int m=0;m<16;m++) a+=sC[o*16+m]*sA[m*16+jj];
    sCA[t]=a; }
  if (t<32){ int o=t>>2, ii=t&3; float a=0.f;
    #pragma unroll
    for(int m=0;m<16;m++) a+=sC[o*16+m]*sB[m*4+ii];
    sCB[t]=a; }
  __syncthreads();

  for (int k=0;k<RS;k++){
    { float a=0.f;                                    // Tm = A @ P
      #pragma unroll
      for(int m=0;m<16;m++) a+=sA[s*16+m]*P[m*16+j];
      Tm[t]=a; }
    __syncthreads();
    { float a=sQ[t];                                  // Pp = Tm A^T + Q
      #pragma unroll
      for(int m=0;m<16;m++) a+=Tm[s*16+m]*sA[j*16+m];
      Pp[t]=a; }
    __syncthreads();
    if (t<128){ int o=t>>4, jj=t&15; float a=0.f;     // CP = C @ Pp
      #pragma unroll
      for(int m=0;m<16;m++) a+=sC[o*16+m]*Pp[m*16+jj];
      CP[t]=a; }
    __syncthreads();
    if (t<64){ int o=t>>3, p=t&7; float a=sR[t];      // S = CP C^T + R
      #pragma unroll
      for(int m=0;m<16;m++) a+=CP[o*16+m]*sC[p*16+m];
      S8[t]=a; }
    __syncthreads();
    if (t==0){                                        // 8x8 SPD inverse via Schur
      float Ai[16]; inv4x4(&S8[0], 8, Ai);
      float W[16];
      #pragma unroll
      for(int i4=0;i4<4;i4++)
        #pragma unroll
        for(int j4=0;j4<4;j4++){ float a=0.f;
          #pragma unroll
          for(int m=0;m<4;m++) a+=S8[(4+i4)*8+m]*Ai[m*4+j4];
          W[i4*4+j4]=a; }
      float Sc[16];
      #pragma unroll
      for(int i4=0;i4<4;i4++)
        #pragma unroll
        for(int j4=0;j4<4;j4++){ float a=S8[(4+i4)*8+4+j4];
          #pragma unroll
          for(int m=0;m<4;m++) a-=W[i4*4+m]*S8[m*8+4+j4];
          Sc[i4*4+j4]=a; }
      float Sci[16]; inv4x4(Sc, 4, Sci);
      float X21[16];
      #pragma unroll
      for(int i4=0;i4<4;i4++)
        #pragma unroll
        for(int j4=0;j4<4;j4++){ float a=0.f;
          #pragma unroll
          for(int m=0;m<4;m++) a+=Sci[i4*4+m]*W[m*4+j4];
          X21[i4*4+j4]=-a; }
      float X11[16];
      #pragma unroll
      for(int i4=0;i4<4;i4++)
        #pragma unroll
        for(int j4=0;j4<4;j4++){ float a=Ai[i4*4+j4];
          #pragma unroll
          for(int m=0;m<4;m++) a-=W[m*4+i4]*X21[m*4+j4];
          X11[i4*4+j4]=a; }
      #pragma unroll
      for(int o=0;o<8;o++)
        #pragma unroll
        for(int p=0;p<8;p++){
          float v;
          if (o<4 && p<4) v=X11[o*4+p];
          else if (o<4)   v=X21[(p-4)*4+o];
          else if (p<4)   v=X21[(o-4)*4+p];
          else            v=Sci[(o-4)*4+(p-4)];
          Sinv[o*8+p]=v; }
    }
    __syncthreads();
    if (t<128){ int ss=t>>3, o=t&7; float a=0.f;      // K = CP^T Sinv
      #pragma unroll
      for(int p=0;p<8;p++) a+=CP[p*16+ss]*Sinv[p*8+o];
      KK[t]=a; }
    __syncthreads();
    { float a=Pp[t], mg=sA[t];                        // P_post, M_k
      #pragma unroll
      for(int o=0;o<8;o++){ float kv=KK[s*8+o]; a-=kv*CP[o*16+j]; mg-=kv*sCA[o*16+j]; }
      P[t]=a;
      g_M[k*256+t]=mg; }
    if (t<128) g_Kg[k*128+t]=KK[t];
    if (t<64){ int ss=t>>2, ii=t&3; float a=sB[t];    // N_k
      #pragma unroll
      for(int o=0;o<8;o++) a-=KK[ss*8+o]*sCB[o*4+ii];
      g_Ng[k*64+t]=a; }
    __syncthreads();
  }

  // Per chunk type tt: suffix products; Wz_j=S_j K_j, Wu_j=S_j N_j; Phi = full product
  for (int tt=0; tt<NTYPE; tt++){
    float* Sb = BufA; float* Sn = BufB;
    Sb[t] = (s==j)?1.f:0.f;
    __syncthreads();
    for (int jj=LCH-1; jj>=0; jj--){
      const int k = (tt==0)? jj : (RS-1);
      if (t<128){ int ss=t>>3, o=t&7; float a=0.f;    // Wz
        #pragma unroll
        for(int m=0;m<16;m++) a+=Sb[ss*16+m]*g_Kg[k*128+m*8+o];
        g_W[(tt*16+ss)*96 + jj*12 + o] = a; }
      else { int e=t-128; int ss=e>>2, ii=e&3;        // Wu
        if (e<64){ float a=0.f;
          #pragma unroll
          for(int m=0;m<16;m++) a+=Sb[ss*16+m]*g_Ng[k*64+m*4+ii];
          g_W[(tt*16+ss)*96 + jj*12 + 8 + ii] = a; } }
      { float a=0.f;                                  // S = S @ M_k
        #pragma unroll
        for(int m=0;m<16;m++) a+=Sb[s*16+m]*g_M[k*256+m*16+j];
        Sn[t]=a; }
      __syncthreads();
      float* tmp=Sb; Sb=Sn; Sn=tmp;
    }
    g_Phi[tt*256+t]=Sb[t];
    __syncthreads();
  }
}

// P1: chunk response from zero state — d[c][:][b] = W(type) @ inputs(chunk c, batch b)
__global__ void __launch_bounds__(TPB) resp_kernel(const float* __restrict__ obs,
                                                   const float* __restrict__ u)
{
  __shared__ ull sW[16*96];                           // duplicated pairs, 12KB
  const int c  = blockIdx.y;
  const int tt = (c==0)?0:1;
  for (int idx=threadIdx.x; idx<16*96; idx+=TPB)
    sW[idx] = fdup(g_W[tt*16*96 + idx]);
  const int b0 = (blockIdx.x*TPB + threadIdx.x)*NB;
  const int k0 = c*LCH;
  ull acc[SDIM];
  #pragma unroll
  for (int s=0;s<SDIM;s++) acc[s]=0ull;
  __syncthreads();

  const float* ob0 = obs + ((size_t)b0*T_SEQ + k0)*ODIM;
  const float* ob1 = ob0 + (size_t)T_SEQ*ODIM;
  const float* uu0 = u   + ((size_t)b0*T_SEQ + k0)*IDIM;
  const float* uu1 = uu0 + (size_t)T_SEQ*IDIM;

  for (int jj=0;jj<LCH;jj++){
    float4 z0a = *(const float4*)(ob0 + jj*ODIM);
    float4 z0b = *(const float4*)(ob0 + jj*ODIM + 4);
    float4 z1a = *(const float4*)(ob1 + jj*ODIM);
    float4 z1b = *(const float4*)(ob1 + jj*ODIM + 4);
    float4 v0  = *(const float4*)(uu0 + jj*IDIM);
    float4 v1  = *(const float4*)(uu1 + jj*IDIM);
    ull ip[12];
    ip[0]=fpair(z0a.x,z1a.x); ip[1]=fpair(z0a.y,z1a.y);
    ip[2]=fpair(z0a.z,z1a.z); ip[3]=fpair(z0a.w,z1a.w);
    ip[4]=fpair(z0b.x,z1b.x); ip[5]=fpair(z0b.y,z1b.y);
    ip[6]=fpair(z0b.z,z1b.z); ip[7]=fpair(z0b.w,z1b.w);
    ip[8]=fpair(v0.x,v1.x);   ip[9]=fpair(v0.y,v1.y);
    ip[10]=fpair(v0.z,v1.z);  ip[11]=fpair(v0.w,v1.w);
    #pragma unroll
    for (int s=0;s<SDIM;s++){
      const ulonglong2* Wr = (const ulonglong2*)&sW[s*96 + jj*12];
      ull a = acc[s];
      #pragma unroll
      for (int q=0;q<6;q++){
        ulonglong2 w = Wr[q];
        ffma2(a, w.x, ip[2*q]);
        ffma2(a, w.y, ip[2*q+1]);
      }
      acc[s]=a;
    }
  }
  #pragma unroll
  for (int s=0;s<SDIM;s++)
    *(ull*)&g_d[((size_t)(c*SDIM+s))*BATCH + b0] = acc[s];
}

// P2: exact serial combine across chunks, one thread per batch.
__global__ void __launch_bounds__(TPB) pass2_kernel(const float* __restrict__ x0)
{
  __shared__ float sPhi[NTYPE*256];
  for (int e=threadIdx.x; e<NTYPE*256; e+=TPB) sPhi[e]=g_Phi[e];
  const int b = blockIdx.x*TPB + threadIdx.x;
  float x[16];
  #pragma unroll
  for(int s=0;s<16;s++) x[s]=x0[s];
  __syncthreads();
  #pragma unroll
  for(int s=0;s<16;s++) g_xs[(size_t)s*BATCH + b]=x[s];
  for (int c=1;c<CH;c++){
    int pidx = (c-1==0)?0:1;
    const float* Phi=&sPhi[pidx*256];
    float dd[16];
    #pragma unroll
    for(int s=0;s<16;s++) dd[s]=g_d[((size_t)((c-1)*16+s))*BATCH + b];
    float xn[16];
    #pragma unroll
    for(int s=0;s<16;s++){
      float a=dd[s];
      #pragma unroll
      for(int jj=0;jj<16;jj++) a+=Phi[s*16+jj]*x[jj];
      xn[s]=a;
    }
    #pragma unroll
    for(int s=0;s<16;s++) x[s]=xn[s];
    #pragma unroll
    for(int s=0;s<16;s++) g_xs[((size_t)(c*16+s))*BATCH + b]=x[s];
  }
}

// P3: monolithic (R7 shape): serial recurrence within chunk from true start state.
__global__ void __launch_bounds__(TPB, 4) pass3_kernel(const float* __restrict__ obs,
                                                       const float* __restrict__ u,
                                                       float* __restrict__ out)
{
  extern __shared__ ull dsm[];                        // [sM 8*256 | sK 8*128 | sN 8*64]
  ull* sM = dsm;
  ull* sK = dsm + LCH*256;
  ull* sN = dsm + LCH*256 + LCH*128;
  const int c  = blockIdx.y;
  const bool trans = (c==0);
  const int nset = trans ? LCH : 1;
  for (int idx=threadIdx.x; idx<nset*256; idx+=TPB){
    int i=idx>>8, e=idx&255; int kk = trans ? i : (RS-1);
    sM[idx]=fdup(g_M[kk*256+e]);
  }
  for (int idx=threadIdx.x; idx<nset*128; idx+=TPB){
    int i=idx>>7, e=idx&127; int kk = trans ? i : (RS-1);
    sK[idx]=fdup(g_Kg[kk*128+e]);
  }
  for (int idx=threadIdx.x; idx<nset*64; idx+=TPB){
    int i=idx>>6, e=idx&63; int kk = trans ? i : (RS-1);
    sN[idx]=fdup(g_Ng[kk*64+e]);
  }
  const int b0 = (blockIdx.x*TPB + threadIdx.x)*NB;
  const int k0 = c*LCH;
  ull xp[SDIM];
  #pragma unroll
  for (int s=0;s<SDIM;s++)
    xp[s] = *(const ull*)&g_xs[((size_t)(c*SDIM+s))*BATCH + b0];
  __syncthreads();

  const float* ob0 = obs + ((size_t)b0*T_SEQ + k0)*ODIM;
  const float* ob1 = ob0 + (size_t)T_SEQ*ODIM;
  const float* uu0 = u   + ((size_t)b0*T_SEQ + k0)*IDIM;
  const float* uu1 = uu0 + (size_t)T_SEQ*IDIM;

  for (int i=0;i<LCH;i++){
    const int mi = trans ? i : 0;
    float4 z0a = *(const float4*)(ob0 + i*ODIM);
    float4 z0b = *(const float4*)(ob0 + i*ODIM + 4);
    float4 z1a = *(const float4*)(ob1 + i*ODIM);
    float4 z1b = *(const float4*)(ob1 + i*ODIM + 4);
    float4 v0  = *(const float4*)(uu0 + i*IDIM);
    float4 v1  = *(const float4*)(uu1 + i*IDIM);
    ull zp[8], up[4];
    zp[0]=fpair(z0a.x,z1a.x); zp[1]=fpair(z0a.y,z1a.y);
    zp[2]=fpair(z0a.z,z1a.z); zp[3]=fpair(z0a.w,z1a.w);
    zp[4]=fpair(z0b.x,z1b.x); zp[5]=fpair(z0b.y,z1b.y);
    zp[6]=fpair(z0b.z,z1b.z); zp[7]=fpair(z0b.w,z1b.w);
    up[0]=fpair(v0.x,v1.x);   up[1]=fpair(v0.y,v1.y);
    up[2]=fpair(v0.z,v1.z);   up[3]=fpair(v0.w,v1.w);

    const ulonglong2* M2 = (const ulonglong2*)&sM[mi*256];
    const ulonglong2* K2 = (const ulonglong2*)&sK[mi*128];
    const ulonglong2* N2 = (const ulonglong2*)&sN[mi*64];
    ull acc[SDIM];
    #pragma unroll
    for (int s=0;s<SDIM;s++){
      ulonglong2 k0p = K2[s*4+0];
      ull a = 0ull;
      ffma2(a, k0p.x, zp[0]); ffma2(a, k0p.y, zp[1]);
      ulonglong2 k1p = K2[s*4+1]; ffma2(a, k1p.x, zp[2]); ffma2(a, k1p.y, zp[3]);
      ulonglong2 k2p = K2[s*4+2]; ffma2(a, k2p.x, zp[4]); ffma2(a, k2p.y, zp[5]);
      ulonglong2 k3p = K2[s*4+3]; ffma2(a, k3p.x, zp[6]); ffma2(a, k3p.y, zp[7]);
      ulonglong2 n0p = N2[s*2+0]; ffma2(a, n0p.x, up[0]); ffma2(a, n0p.y, up[1]);
      ulonglong2 n1p = N2[s*2+1]; ffma2(a, n1p.x, up[2]); ffma2(a, n1p.y, up[3]);
      acc[s]=a;
    }
    #pragma unroll
    for (int s=0;s<SDIM;s++){
      ull a = acc[s];
      #pragma unroll
      for (int jj=0;jj<8;jj++){
        ulonglong2 mm = M2[s*8+jj];
        ffma2(a, mm.x, xp[2*jj]);
        ffma2(a, mm.y, xp[2*jj+1]);
      }
      acc[s]=a;
    }
    #pragma unroll
    for (int s=0;s<SDIM;s++) xp[s]=acc[s];

    {
      float a0[SDIM], a1[SDIM];
      #pragma unroll
      for (int s=0;s<SDIM;s++) unpack2(xp[s], a0[s], a1[s]);
      float4* o0 = (float4*)(out + (((size_t)b0*T_SEQ) + (size_t)(k0+i))*SDIM);
      float4* o1 = (float4*)(out + (((size_t)(b0+1)*T_SEQ) + (size_t)(k0+i))*SDIM);
      o0[0]=make_float4(a0[0],a0[1],a0[2],a0[3]);
      o0[1]=make_float4(a0[4],a0[5],a0[6],a0[7]);
      o0[2]=make_float4(a0[8],a0[9],a0[10],a0[11]);
      o0[3]=make_float4(a0[12],a0[13],a0[14],a0[15]);
      o1[0]=make_float4(a1[0],a1[1],a1[2],a1[3]);
      o1[1]=make_float4(a1[4],a1[5],a1[6],a1[7]);
      o1[2]=make_float4(a1[8],a1[9],a1[10],a1[11]);
      o1[3]=make_float4(a1[12],a1[13],a1[14],a1[15]);
    }
  }
}

extern "C" void kernel_launch(void* const* d_in, const int* in_sizes, int n_in,
                              void* d_out, int out_size)
{
  const float* obs = (const float*)d_in[0];
  const float* u   = (const float*)d_in[1];
  const float* A   = (const float*)d_in[2];
  const float* B   = (const float*)d_in[3];
  const float* C   = (const float*)d_in[4];
  const float* Q   = (const float*)d_in[5];
  const float* R   = (const float*)d_in[6];
  const float* x0  = (const float*)d_in[7];
  float* out = (float*)d_out;

  riccati_kernel<<<1, 256>>>(A, B, C, Q, R);

  dim3 gridR(BATCH/(TPB*NB), CH);
  resp_kernel<<<gridR, TPB>>>(obs, u);
  pass2_kernel<<<BATCH/TPB, TPB>>>(x0);

  const int dynsmem = (LCH*256 + LCH*128 + LCH*64) * (int)sizeof(ull); // 28672
  pass3_kernel<<<gridR, TPB, dynsmem>>>(obs, u, out);
}